// round 16
// baseline (speedup 1.0000x reference)
#include <cuda_runtime.h>
#include <math.h>

#define H 256
#define DIN 700
#define DOUT 20
#define BATCH 128
#define TT 250

// Scratch (device globals). g_X1 is T-MAJOR: X1[t][b][i].
// Weight tables have an extra all-zero row (index 256) for padded gathers.
__device__ float g_X1[(size_t)TT * BATCH * H];
__device__ float g_W11T[(H + 1) * H];
__device__ float g_W12T[(H + 1) * H];
__device__ float g_W22T[(H + 1) * H];

// ---------------------------------------------------------------------------
__device__ __forceinline__ void ffma2(unsigned long long& acc,
                                      unsigned long long a,
                                      unsigned long long b) {
    asm("fma.rn.f32x2 %0, %1, %2, %0;" : "+l"(acc) : "l"(a), "l"(b));
}
__device__ __forceinline__ unsigned long long pack2(float lo, float hi) {
    unsigned long long r;
    asm("mov.b64 %0, {%1, %2};" : "=l"(r) : "f"(lo), "f"(hi));
    return r;
}
__device__ __forceinline__ void unpack2(unsigned long long v, float& lo, float& hi) {
    asm("mov.b64 {%0, %1}, %2;" : "=f"(lo), "=f"(hi) : "l"(v));
}
// Packed fp32 pair add (two independent rn adds -> bitwise == scalar adds).
__device__ __forceinline__ unsigned long long addp(unsigned long long a,
                                                   unsigned long long b) {
    unsigned long long r;
    asm("add.rn.f32x2 %0, %1, %2;" : "=l"(r) : "l"(a), "l"(b));
    return r;
}
// Named barrier over the 512 worker threads (warps 0-15).
__device__ __forceinline__ void bar_workers() {
    asm volatile("bar.sync 1, 512;" ::: "memory");
}
// Step-boundary producer/consumer barrier (id 2, 544 threads total).
__device__ __forceinline__ void bar_step_arrive() {
    asm volatile("bar.arrive 2, 544;" ::: "memory");
}
__device__ __forceinline__ void bar_step_sync() {
    asm volatile("bar.sync 2, 544;" ::: "memory");
}

// ---------------------------------------------------------------------------
__global__ void transpose_weights_kernel(const float* __restrict__ W11,
                                         const float* __restrict__ W12,
                                         const float* __restrict__ W22) {
    int idx = blockIdx.x * blockDim.x + threadIdx.x;
    if (idx < 3 * H * H) {
        int m = idx >> 16;
        int r = (idx >> 8) & 255;
        int c = idx & 255;
        if (m == 0)      g_W11T[c * H + r] = W11[r * H + c];
        else if (m == 1) g_W12T[c * H + r] = W12[r * H + c];
        else             g_W22T[c * H + r] = W22[r * H + c];
    } else {
        int w = idx - 3 * H * H;
        if (w < 3 * H) {
            int m = w >> 8, c = w & 255;
            if (m == 0)      g_W11T[256 * H + c] = 0.f;
            else if (m == 1) g_W12T[256 * H + c] = 0.f;
            else             g_W22T[256 * H + c] = 0.f;
        }
    }
}

// ---------------------------------------------------------------------------
// X1[t][b][:] = x[b][t][:] @ Wi1.T + (bi1 + b11). Block y == timestep.
// (Proven serial GEMM, unchanged.)
// ---------------------------------------------------------------------------
#define GBM 128
#define GBN 128
#define GBK 16
#define GPAD 4
#define GNT ((DIN + GBK - 1) / GBK)

__global__ __launch_bounds__(256, 2) void gemm_x1_kernel(
    const float* __restrict__ x, const float* __restrict__ Wi1,
    const float* __restrict__ bi1, const float* __restrict__ b11) {
    __shared__ float As[2][GBK][GBM + GPAD];
    __shared__ float Bs[2][GBK][GBN + GPAD];

    int tid = threadIdx.x;
    int tstep = blockIdx.y;
    int n0 = blockIdx.x * GBN;
    int tx = tid & 15, ty = tid >> 4;

    int row0 = tid >> 2,          kc0 = tid & 3;
    int row1 = (256 + tid) >> 2,  kc1 = tid & 3;

    const float* xr0 = x + ((size_t)row0 * TT + tstep) * DIN;
    const float* xr1 = x + ((size_t)row1 * TT + tstep) * DIN;

    unsigned long long acc[4][8];
#pragma unroll
    for (int r = 0; r < 4; ++r)
#pragma unroll
        for (int c = 0; c < 8; ++c) acc[r][c] = 0ull;

    float4 stA0, stA1, stB0, stB1;

    {
        int kA0 = kc0 * 4, kA1 = kc1 * 4;
        stA0 = *(const float4*)(xr0 + kA0);
        stA1 = *(const float4*)(xr1 + kA1);
        stB0 = *(const float4*)(Wi1 + (size_t)(n0 + row0) * DIN + kA0);
        stB1 = *(const float4*)(Wi1 + (size_t)(n0 + row1) * DIN + kA1);
        As[0][kc0 * 4 + 0][row0] = stA0.x; As[0][kc0 * 4 + 1][row0] = stA0.y;
        As[0][kc0 * 4 + 2][row0] = stA0.z; As[0][kc0 * 4 + 3][row0] = stA0.w;
        As[0][kc1 * 4 + 0][row1] = stA1.x; As[0][kc1 * 4 + 1][row1] = stA1.y;
        As[0][kc1 * 4 + 2][row1] = stA1.z; As[0][kc1 * 4 + 3][row1] = stA1.w;
        Bs[0][kc0 * 4 + 0][row0] = stB0.x; Bs[0][kc0 * 4 + 1][row0] = stB0.y;
        Bs[0][kc0 * 4 + 2][row0] = stB0.z; Bs[0][kc0 * 4 + 3][row0] = stB0.w;
        Bs[0][kc1 * 4 + 0][row1] = stB1.x; Bs[0][kc1 * 4 + 1][row1] = stB1.y;
        Bs[0][kc1 * 4 + 2][row1] = stB1.z; Bs[0][kc1 * 4 + 3][row1] = stB1.w;
    }
    __syncthreads();

    for (int t = 0; t < GNT; ++t) {
        int buf = t & 1;

        if (t + 1 < GNT) {
            int kb = (t + 1) * GBK;
            int kA0 = kb + kc0 * 4, kA1 = kb + kc1 * 4;
            stA0 = (kA0 < DIN) ? *(const float4*)(xr0 + kA0) : make_float4(0.f,0.f,0.f,0.f);
            stA1 = (kA1 < DIN) ? *(const float4*)(xr1 + kA1) : make_float4(0.f,0.f,0.f,0.f);
            stB0 = (kA0 < DIN) ? *(const float4*)(Wi1 + (size_t)(n0 + row0) * DIN + kA0)
                               : make_float4(0.f, 0.f, 0.f, 0.f);
            stB1 = (kA1 < DIN) ? *(const float4*)(Wi1 + (size_t)(n0 + row1) * DIN + kA1)
                               : make_float4(0.f, 0.f, 0.f, 0.f);
        }

#pragma unroll
        for (int kk = 0; kk < GBK; ++kk) {
            ulonglong2 aA = *(const ulonglong2*)&As[buf][kk][ty * 8];
            ulonglong2 aB = *(const ulonglong2*)&As[buf][kk][ty * 8 + 4];
            float4 b0 = *(const float4*)&Bs[buf][kk][tx * 8];
            float4 b1 = *(const float4*)&Bs[buf][kk][tx * 8 + 4];
            float barr[8] = {b0.x, b0.y, b0.z, b0.w, b1.x, b1.y, b1.z, b1.w};
#pragma unroll
            for (int c = 0; c < 8; ++c) {
                unsigned long long bb = pack2(barr[c], barr[c]);
                ffma2(acc[0][c], aA.x, bb);
                ffma2(acc[1][c], aA.y, bb);
                ffma2(acc[2][c], aB.x, bb);
                ffma2(acc[3][c], aB.y, bb);
            }
        }

        if (t + 1 < GNT) {
            int nb = buf ^ 1;
            As[nb][kc0 * 4 + 0][row0] = stA0.x; As[nb][kc0 * 4 + 1][row0] = stA0.y;
            As[nb][kc0 * 4 + 2][row0] = stA0.z; As[nb][kc0 * 4 + 3][row0] = stA0.w;
            As[nb][kc1 * 4 + 0][row1] = stA1.x; As[nb][kc1 * 4 + 1][row1] = stA1.y;
            As[nb][kc1 * 4 + 2][row1] = stA1.z; As[nb][kc1 * 4 + 3][row1] = stA1.w;
            Bs[nb][kc0 * 4 + 0][row0] = stB0.x; Bs[nb][kc0 * 4 + 1][row0] = stB0.y;
            Bs[nb][kc0 * 4 + 2][row0] = stB0.z; Bs[nb][kc0 * 4 + 3][row0] = stB0.w;
            Bs[nb][kc1 * 4 + 0][row1] = stB1.x; Bs[nb][kc1 * 4 + 1][row1] = stB1.y;
            Bs[nb][kc1 * 4 + 2][row1] = stB1.z; Bs[nb][kc1 * 4 + 3][row1] = stB1.w;
        }
        __syncthreads();
    }

    float bias[8];
#pragma unroll
    for (int c = 0; c < 8; ++c) {
        int n = n0 + tx * 8 + c;
        bias[c] = bi1[n] + b11[n];
    }
    float* X1t = g_X1 + (size_t)tstep * BATCH * H;
#pragma unroll
    for (int r2 = 0; r2 < 4; ++r2) {
        float lo[8], hi[8];
#pragma unroll
        for (int c = 0; c < 8; ++c) unpack2(acc[r2][c], lo[c], hi[c]);
        int bA = ty * 8 + 2 * r2;
        int bB = bA + 1;
        int n = n0 + tx * 8;
        float4* pA = (float4*)(X1t + (size_t)bA * H + n);
        float4* pB = (float4*)(X1t + (size_t)bB * H + n);
        pA[0] = make_float4(lo[0] + bias[0], lo[1] + bias[1], lo[2] + bias[2], lo[3] + bias[3]);
        pA[1] = make_float4(lo[4] + bias[4], lo[5] + bias[5], lo[6] + bias[6], lo[7] + bias[7]);
        pB[0] = make_float4(hi[0] + bias[0], hi[1] + bias[1], hi[2] + bias[2], hi[3] + bias[3]);
        pB[1] = make_float4(hi[4] + bias[4], hi[5] + bias[5], hi[6] + bias[6], hi[7] + bias[7]);
    }
}

// ---------------------------------------------------------------------------
// Packed gather: sum 4 rows' float4 slices with add.rn.f32x2 (bitwise
// identical to scalar adds, half the FMA-pipe issue).
// ---------------------------------------------------------------------------
__device__ __forceinline__ void acc4p(const float* __restrict__ W,
                                      int4 j, int col,
                                      unsigned long long& hxy,
                                      unsigned long long& hzw) {
    ulonglong2 v0 = *(const ulonglong2*)(W + j.x * H + col);
    ulonglong2 v1 = *(const ulonglong2*)(W + j.y * H + col);
    ulonglong2 v2 = *(const ulonglong2*)(W + j.z * H + col);
    ulonglong2 v3 = *(const ulonglong2*)(W + j.w * H + col);
    hxy = addp(hxy, addp(addp(v0.x, v1.x), addp(v2.x, v3.x)));
    hzw = addp(hzw, addp(addp(v0.y, v1.y), addp(v2.y, v3.y)));
}

// ---------------------------------------------------------------------------
// Persistent RNN: one CTA per sample, 544 threads.
//   warps 0-15: workers (segmented lists, rotated chunks, packed adds,
//     decay-prep hoisted into gather phases; step boundary = bar.arrive).
//   warp 16: output-only — bar.sync each step, then walks list2[pn]
//     itself (pads hit sWoT zero row) + softmax, with a full step of slack.
// ---------------------------------------------------------------------------
__global__ __launch_bounds__(544, 1) void rnn_kernel(
    const float* __restrict__ mem1_0, const float* __restrict__ mem2_0,
    const float* __restrict__ memo_0,
    const float* __restrict__ b12v, const float* __restrict__ b22v,
    const float* __restrict__ Wo, const float* __restrict__ bov,
    const float* __restrict__ tau_adp1, const float* __restrict__ tau_adp2,
    const float* __restrict__ tau_m1, const float* __restrict__ tau_m2,
    const float* __restrict__ tau_mo,
    float* __restrict__ out) {
    __shared__ __align__(16) int list1[2][H];
    __shared__ __align__(16) int list2[2][H];
    __shared__ __align__(16) int cntp1[2][8];
    __shared__ __align__(16) int cntp2[2][8];
    __shared__ float part11[8][H];
    __shared__ float part22[8][H];
    __shared__ float part12[8][H];
    __shared__ float sWoT[(H + 1) * DOUT];

    int b = blockIdx.x;
    int tid = threadIdx.x;
    bool is_worker = tid < 512;
    int lane = tid & 31, warp = tid >> 5;
    int rep = (tid >> 6) & 7;
    int col = (tid & 63) << 2;

    for (int idx = tid; idx < H * DOUT; idx += 544) {
        int j = idx / DOUT, k = idx - j * DOUT;
        sWoT[idx] = Wo[k * H + j];
    }
    if (tid < DOUT) sWoT[H * DOUT + tid] = 0.f;
    if (tid < 8) {
        cntp1[0][tid] = 0; cntp1[1][tid] = 0;
        cntp2[0][tid] = 0; cntp2[1][tid] = 0;
    }

    // worker (owner) state
    float mem1 = 0.f, sp1 = 0.f, ab1 = 0.01f, al1 = 0.f, ro1 = 0.f;
    float oma1 = 0.f, oro1 = 0.f;
    float mem2 = 0.f, sp2 = 0.f, ab2 = 0.01f, al2 = 0.f, ro2 = 0.f;
    float oma2 = 0.f, oro2 = 0.f;
    float hb2 = 0.f;
    if (is_worker && tid < 256) {
        mem1 = mem1_0[b * H + tid];
        al1 = expf(-1.f / tau_m1[tid]);  oma1 = 1.f - al1;
        ro1 = expf(-1.f / tau_adp1[tid]); oro1 = 1.f - ro1;
        mem2 = mem2_0[b * H + tid];
        al2 = expf(-1.f / tau_m2[tid]);  oma2 = 1.f - al2;
        ro2 = expf(-1.f / tau_adp2[tid]); oro2 = 1.f - ro2;
        hb2 = b12v[tid] + b22v[tid];
    }
    // output-warp state (warp 16)
    float memo = 0.f, alo = 0.f, omo = 0.f, bok = 0.f, accv = 0.f;
    if (!is_worker && lane < DOUT) {
        memo = memo_0[b * DOUT + lane];
        alo = expf(-1.f / tau_mo[lane]); omo = 1.f - alo;
        bok = bov[lane];
    }
    __syncthreads();

    if (is_worker) {
        int p = 0;
        float x1cur = 0.f, x1n1 = 0.f;
        if (tid < 256) {
            x1cur = g_X1[(size_t)b * H + tid];
            x1n1  = g_X1[((size_t)BATCH + b) * H + tid];
        }

        for (int t = 0; t < TT; ++t) {
            int pn = p ^ 1;

            float x1n2 = 0.f;
            if (tid < 256 && t + 2 < TT)
                x1n2 = g_X1[((size_t)(t + 2) * BATCH + b) * H + tid];

            // ---- phase A: W11 gather (old sp1) + hoisted layer-1 prep ----
            float B1 = 0.f, base1 = 0.f;
            {
                int cc[8];
                *(int4*)&cc[0] = *(const int4*)&cntp1[p][0];
                *(int4*)&cc[4] = *(const int4*)&cntp1[p][4];
                unsigned long long a11xy = 0ull, a11zw = 0ull;
#pragma unroll
                for (int seg = 0; seg < 8; ++seg) {
                    int ch = (rep + seg) & 7;
                    const int4* s1 = (const int4*)&list1[p][seg << 5];
                    if ((ch << 2) < cc[seg]) acc4p(g_W11T, s1[ch], col, a11xy, a11zw);
                }
                *(ulonglong2*)&part11[rep][col] = make_ulonglong2(a11xy, a11zw);
                if (tid < 256) {
                    ab1 = ro1 * ab1 + oro1 * sp1;
                    B1 = 0.01f + 1.8f * ab1;
                    base1 = mem1 * al1 - B1 * sp1;
                }
            }
            bar_workers();   // (a)

            // ---- layer 1 update + segmented list write (owners) ----
            if (tid < 256) {
                float s0 = part11[0][tid] + part11[1][tid];
                float s1v = part11[2][tid] + part11[3][tid];
                float s2 = part11[4][tid] + part11[5][tid];
                float s3 = part11[6][tid] + part11[7][tid];
                float h1 = x1cur + ((s0 + s1v) + (s2 + s3));
                mem1 = base1 + oma1 * h1;
                float sp1n = (mem1 - B1) > 0.f ? 1.f : 0.f;
                unsigned bal = __ballot_sync(0xffffffffu, sp1n != 0.f);
                int cw = __popc(bal);
                int cwp = (cw + 3) & ~3;
                unsigned ltm = (1u << lane) - 1u;
                if (sp1n != 0.f) {
                    list1[pn][(warp << 5) + __popc(bal & ltm)] = tid;
                } else {
                    int np = __popc(~bal & ltm);
                    if (np < cwp - cw) list1[pn][(warp << 5) + cw + np] = 256;
                }
                if (lane == 0) cntp1[pn][warp] = cwp;
                sp1 = sp1n;
            }
            bar_workers();   // (b)

            // ---- phase B: W12 (new sp1) + W22 (old sp2) + layer-2 prep ----
            float B2 = 0.f, base2 = 0.f;
            {
                int c1[8], c2[8];
                *(int4*)&c1[0] = *(const int4*)&cntp1[pn][0];
                *(int4*)&c1[4] = *(const int4*)&cntp1[pn][4];
                *(int4*)&c2[0] = *(const int4*)&cntp2[p][0];
                *(int4*)&c2[4] = *(const int4*)&cntp2[p][4];
                unsigned long long a12xy = 0ull, a12zw = 0ull;
                unsigned long long a22xy = 0ull, a22zw = 0ull;
#pragma unroll
                for (int seg = 0; seg < 8; ++seg) {
                    int ch = (rep + seg) & 7;
                    int c4 = ch << 2;
                    const int4* s1 = (const int4*)&list1[pn][seg << 5];
                    const int4* s2 = (const int4*)&list2[p][seg << 5];
                    if (c4 < c1[seg]) acc4p(g_W12T, s1[ch], col, a12xy, a12zw);
                    if (c4 < c2[seg]) acc4p(g_W22T, s2[ch], col, a22xy, a22zw);
                }
                *(ulonglong2*)&part12[rep][col] = make_ulonglong2(a12xy, a12zw);
                *(ulonglong2*)&part22[rep][col] = make_ulonglong2(a22xy, a22zw);
                if (tid < 256) {
                    ab2 = ro2 * ab2 + oro2 * sp2;
                    B2 = 0.01f + 1.8f * ab2;
                    base2 = mem2 * al2 - B2 * sp2;
                }
            }
            bar_workers();   // (c)

            // ---- layer 2 update + list write (owners); pout moved out ----
            if (tid < 256) {
                float u0 = part12[0][tid] + part12[1][tid];
                float u1v = part12[2][tid] + part12[3][tid];
                float u2v = part12[4][tid] + part12[5][tid];
                float u3 = part12[6][tid] + part12[7][tid];
                float v0 = part22[0][tid] + part22[1][tid];
                float v1v = part22[2][tid] + part22[3][tid];
                float v2v = part22[4][tid] + part22[5][tid];
                float v3 = part22[6][tid] + part22[7][tid];
                float h2 = hb2 + ((u0 + u1v) + (u2v + u3)) + ((v0 + v1v) + (v2v + v3));
                mem2 = base2 + oma2 * h2;
                float sp2n = (mem2 - B2) > 0.f ? 1.f : 0.f;
                unsigned bal = __ballot_sync(0xffffffffu, sp2n != 0.f);
                int cw = __popc(bal);
                int cwp = (cw + 3) & ~3;
                unsigned ltm = (1u << lane) - 1u;
                if (sp2n != 0.f) {
                    list2[pn][(warp << 5) + __popc(bal & ltm)] = tid;
                } else {
                    int np = __popc(~bal & ltm);
                    if (np < cwp - cw) list2[pn][(warp << 5) + cw + np] = 256;
                }
                if (lane == 0) cntp2[pn][warp] = cwp;
                sp2 = sp2n;
            }
            bar_step_arrive();   // (d) non-blocking for workers

            p = pn;
            x1cur = x1n1;
            x1n1 = x1n2;
        }
    } else {
        // ---- warp 16: output gather + softmax, one full step of slack ----
        int p = 0;
        int kk = lane < DOUT ? lane : 0;
        for (int t = 0; t < TT; ++t) {
            int pn = p ^ 1;
            bar_step_sync();   // (d) of step t — orders list2/cntp2 writes
            float o = bok;
#pragma unroll
            for (int seg = 0; seg < 8; ++seg) {
                int c = cntp2[pn][seg];
                const int* ls = &list2[pn][seg << 5];
                for (int q = 0; q < c; ++q)
                    o += sWoT[ls[q] * DOUT + kk];   // pads -> zero row 256
            }
            memo = memo * alo + omo * o;
            if (t > 10) {
                float e = lane < DOUT ? __expf(memo) : 0.f;
                float ss = e;
#pragma unroll
                for (int sh = 16; sh > 0; sh >>= 1)
                    ss += __shfl_xor_sync(0xffffffffu, ss, sh);
                accv += e / ss;
            }
            p = pn;
        }
        if (lane < DOUT) out[b * DOUT + lane] = accv;
    }
}

// ---------------------------------------------------------------------------
// Serial single-stream launch (overlap permanently abandoned: R6/R8/R11).
// ---------------------------------------------------------------------------
extern "C" void kernel_launch(void* const* d_in, const int* in_sizes, int n_in,
                              void* d_out, int out_size) {
    const float* x        = (const float*)d_in[0];
    const float* mem1_0   = (const float*)d_in[1];
    const float* mem2_0   = (const float*)d_in[2];
    const float* memo_0   = (const float*)d_in[3];
    const float* Wi1      = (const float*)d_in[4];
    const float* bi1      = (const float*)d_in[5];
    const float* W11      = (const float*)d_in[6];
    const float* b11      = (const float*)d_in[7];
    const float* W12      = (const float*)d_in[8];
    const float* b12      = (const float*)d_in[9];
    const float* W22      = (const float*)d_in[10];
    const float* b22      = (const float*)d_in[11];
    const float* Wo       = (const float*)d_in[12];
    const float* bo       = (const float*)d_in[13];
    const float* tau_adp1 = (const float*)d_in[14];
    const float* tau_adp2 = (const float*)d_in[15];
    const float* tau_m1   = (const float*)d_in[16];
    const float* tau_m2   = (const float*)d_in[17];
    const float* tau_mo   = (const float*)d_in[18];
    float* out = (float*)d_out;

    transpose_weights_kernel<<<(3 * H * H + 3 * H + 255) / 256, 256>>>(W11, W12, W22);
    dim3 g(H / GBN, TT);   // (2, 250): block y == timestep
    gemm_x1_kernel<<<g, 256>>>(x, Wi1, bi1, b11);
    rnn_kernel<<<BATCH, 544>>>(mem1_0, mem2_0, memo_0, b12, b22, Wo, bo,
                               tau_adp1, tau_adp2, tau_m1, tau_m2, tau_mo, out);
}